// round 3
// baseline (speedup 1.0000x reference)
#include <cuda_runtime.h>
#include <cstdint>

#define B_  32
#define N_  1024
#define D_  128
#define NDF (N_*D_)          // 131072 per batch per tensor
#define TOT (B_*N_*D_)       // 4194304
#define NSEG 64
#define SEG_BLOCKS 32        // 131072/4096
#define RADIX_BLOCKS (NSEG*SEG_BLOCKS)

// ---------------- device scratch ----------------
__device__ float    g_normP[B_*N_];
__device__ float    g_normT[B_*N_];
__device__ unsigned g_m1[B_*N_];       // min_i d^2 (float bits)
__device__ unsigned g_m2[N_*N_];       // min_b d^2 (float bits)
__device__ double   g_mae, g_s1, g_s2;
__device__ double   g_emd[B_];
__device__ unsigned g_buf0[NSEG*NDF];
__device__ unsigned g_buf1[NSEG*NDF];
__device__ unsigned g_hist[RADIX_BLOCKS*256];

// ---------------- helpers ----------------
__device__ __forceinline__ unsigned f2tf(float x) {
    unsigned r; asm("cvt.rna.tf32.f32 %0, %1;" : "=r"(r) : "f"(x)); return r;
}
__device__ __forceinline__ void mma_tf32(float* c, const unsigned* a, const unsigned* b) {
    asm volatile(
        "mma.sync.aligned.m16n8k8.row.col.f32.tf32.tf32.f32 "
        "{%0,%1,%2,%3}, {%4,%5,%6,%7}, {%8,%9}, {%0,%1,%2,%3};\n"
        : "+f"(c[0]), "+f"(c[1]), "+f"(c[2]), "+f"(c[3])
        : "r"(a[0]), "r"(a[1]), "r"(a[2]), "r"(a[3]), "r"(b[0]), "r"(b[1]));
}
__device__ __forceinline__ float blockReduceSum(float v) {
    #pragma unroll
    for (int o = 16; o; o >>= 1) v += __shfl_xor_sync(0xffffffffu, v, o);
    __shared__ float sm[8];
    int lane = threadIdx.x & 31, w = threadIdx.x >> 5;
    if (lane == 0) sm[w] = v;
    __syncthreads();
    if (w == 0) {
        v = (lane < 8) ? sm[lane] : 0.f;
        #pragma unroll
        for (int o = 4; o; o >>= 1) v += __shfl_xor_sync(0xffffffffu, v, o);
    }
    return v;  // valid on thread 0
}
__device__ __forceinline__ float keydec(unsigned u) {
    unsigned bits = (u & 0x80000000u) ? (u ^ 0x80000000u) : ~u;
    return __uint_as_float(bits);
}

// ---------------- init ----------------
__global__ void k_init() {
    int i = blockIdx.x * blockDim.x + threadIdx.x;
    int stride = gridDim.x * blockDim.x;
    for (int x = i; x < N_*N_; x += stride) g_m2[x] = 0x7F800000u;
    for (int x = i; x < B_*N_; x += stride) g_m1[x] = 0x7F800000u;
    if (i == 0) { g_mae = 0.0; g_s1 = 0.0; g_s2 = 0.0; }
    if (i < B_) g_emd[i] = 0.0;
}

// ---------------- MAE + row squared norms (warp per row) ----------------
__global__ void k_maenorm(const float* __restrict__ pred, const float* __restrict__ target) {
    const int lane = threadIdx.x & 31;
    const int gw = (blockIdx.x * blockDim.x + threadIdx.x) >> 5;
    const int nw = (gridDim.x * blockDim.x) >> 5;
    float macc = 0.f;
    for (int row = gw; row < B_*N_; row += nw) {
        float4 p = reinterpret_cast<const float4*>(pred)[row*32 + lane];
        float4 t = reinterpret_cast<const float4*>(target)[row*32 + lane];
        float np = p.x*p.x + p.y*p.y + p.z*p.z + p.w*p.w;
        float nt = t.x*t.x + t.y*t.y + t.z*t.z + t.w*t.w;
        float m  = fabsf(p.x-t.x)+fabsf(p.y-t.y)+fabsf(p.z-t.z)+fabsf(p.w-t.w);
        #pragma unroll
        for (int o = 16; o; o >>= 1) {
            np += __shfl_xor_sync(0xffffffffu, np, o);
            nt += __shfl_xor_sync(0xffffffffu, nt, o);
            m  += __shfl_xor_sync(0xffffffffu, m,  o);
        }
        if (lane == 0) { g_normP[row] = np; g_normT[row] = nt; macc += m; }
    }
    __shared__ float bsum;
    if (threadIdx.x == 0) bsum = 0.f;
    __syncthreads();
    if (lane == 0) atomicAdd(&bsum, macc);
    __syncthreads();
    if (threadIdx.x == 0) atomicAdd(&g_mae, (double)bsum);
}

// ---------------- chamfer: tf32 MMA over squared distances ----------------
#define TI 128
#define TJ 128
#define BB 8
#define PAD 132
#define CHAM_SMEM ((2*128*PAD + 256) * 4)

__global__ void __launch_bounds__(256, 1)
k_chamfer(const float* __restrict__ pred, const float* __restrict__ target) {
    extern __shared__ unsigned smem_u[];
    unsigned* As = smem_u;                 // [128][PAD]
    unsigned* Bs = smem_u + 128*PAD;       // [128][PAD]
    float* sNp = (float*)(smem_u + 2*128*PAD);  // [128]
    float* sNt = sNp + 128;                     // [128]

    const int tid  = threadIdx.x;
    const int lane = tid & 31;
    const int warp = tid >> 5;
    const int wi = warp >> 1;   // 0..3
    const int wj = warp & 1;    // 0..1
    const int g  = lane >> 2;   // 0..7
    const int cc = lane & 3;    // 0..3

    const int i0 = blockIdx.x * TI;
    const int j0 = blockIdx.y * TJ;
    const int b0 = blockIdx.z * BB;

    float dmin[2][8][4];
    #pragma unroll
    for (int mt = 0; mt < 2; mt++)
        #pragma unroll
        for (int nt = 0; nt < 8; nt++)
            #pragma unroll
            for (int q = 0; q < 4; q++) dmin[mt][nt][q] = 3.4e38f;

    for (int bi = 0; bi < BB; ++bi) {
        const int b = b0 + bi;
        __syncthreads();
        {
            const float4* Ag = reinterpret_cast<const float4*>(pred   + ((size_t)b*N_ + i0) * D_);
            const float4* Bg = reinterpret_cast<const float4*>(target + ((size_t)b*N_ + j0) * D_);
            #pragma unroll
            for (int r = 0; r < 16; ++r) {
                int idx = r*256 + tid;
                int row = idx >> 5, c4 = idx & 31;
                float4 va = Ag[row*32 + c4];
                float4 vb = Bg[row*32 + c4];
                uint4 ua = make_uint4(f2tf(va.x), f2tf(va.y), f2tf(va.z), f2tf(va.w));
                uint4 ub = make_uint4(f2tf(vb.x), f2tf(vb.y), f2tf(vb.z), f2tf(vb.w));
                *reinterpret_cast<uint4*>(&As[row*PAD + c4*4]) = ua;
                *reinterpret_cast<uint4*>(&Bs[row*PAD + c4*4]) = ub;
            }
            if (tid < 128) sNp[tid] = g_normP[b*N_ + i0 + tid];
            else           sNt[tid-128] = g_normT[b*N_ + j0 + (tid-128)];
        }
        __syncthreads();

        float acc[2][8][4];
        #pragma unroll
        for (int mt = 0; mt < 2; mt++)
            #pragma unroll
            for (int nt = 0; nt < 8; nt++)
                #pragma unroll
                for (int q = 0; q < 4; q++) acc[mt][nt][q] = 0.f;

        #pragma unroll 4
        for (int k0 = 0; k0 < D_; k0 += 8) {
            unsigned a[2][4], bf[8][2];
            #pragma unroll
            for (int mt = 0; mt < 2; ++mt) {
                int r0 = wi*32 + mt*16 + g;
                a[mt][0] = As[r0*PAD + k0 + cc];
                a[mt][1] = As[(r0+8)*PAD + k0 + cc];
                a[mt][2] = As[r0*PAD + k0 + cc + 4];
                a[mt][3] = As[(r0+8)*PAD + k0 + cc + 4];
            }
            #pragma unroll
            for (int nt = 0; nt < 8; ++nt) {
                int jr = wj*64 + nt*8 + g;
                bf[nt][0] = Bs[jr*PAD + k0 + cc];
                bf[nt][1] = Bs[jr*PAD + k0 + cc + 4];
            }
            #pragma unroll
            for (int mt = 0; mt < 2; ++mt)
                #pragma unroll
                for (int nt = 0; nt < 8; ++nt)
                    mma_tf32(acc[mt][nt], a[mt], bf[nt]);
        }

        float nP[2][2];
        #pragma unroll
        for (int mt = 0; mt < 2; ++mt) {
            int r0 = wi*32 + mt*16 + g;
            nP[mt][0] = sNp[r0];
            nP[mt][1] = sNp[r0+8];
        }
        #pragma unroll
        for (int nt = 0; nt < 8; ++nt) {
            int cA = wj*64 + nt*8 + 2*cc;
            float nt0 = sNt[cA], nt1 = sNt[cA+1];
            float cm0 = 3.4e38f, cm1 = 3.4e38f;
            #pragma unroll
            for (int mt = 0; mt < 2; ++mt) {
                float s0 = fmaxf(fmaf(-2.f, acc[mt][nt][0], nP[mt][0] + nt0), 1e-12f);
                float s1 = fmaxf(fmaf(-2.f, acc[mt][nt][1], nP[mt][0] + nt1), 1e-12f);
                float s2 = fmaxf(fmaf(-2.f, acc[mt][nt][2], nP[mt][1] + nt0), 1e-12f);
                float s3 = fmaxf(fmaf(-2.f, acc[mt][nt][3], nP[mt][1] + nt1), 1e-12f);
                dmin[mt][nt][0] = fminf(dmin[mt][nt][0], s0);
                dmin[mt][nt][1] = fminf(dmin[mt][nt][1], s1);
                dmin[mt][nt][2] = fminf(dmin[mt][nt][2], s2);
                dmin[mt][nt][3] = fminf(dmin[mt][nt][3], s3);
                cm0 = fminf(cm0, fminf(s0, s2));
                cm1 = fminf(cm1, fminf(s1, s3));
            }
            #pragma unroll
            for (int o = 4; o <= 16; o <<= 1) {
                cm0 = fminf(cm0, __shfl_xor_sync(0xffffffffu, cm0, o));
                cm1 = fminf(cm1, __shfl_xor_sync(0xffffffffu, cm1, o));
            }
            if (g == 0) {
                atomicMin(&g_m1[b*N_ + j0 + cA],     __float_as_uint(cm0));
                atomicMin(&g_m1[b*N_ + j0 + cA + 1], __float_as_uint(cm1));
            }
        }
    }

    #pragma unroll
    for (int mt = 0; mt < 2; ++mt) {
        int r0 = i0 + wi*32 + mt*16 + g;
        #pragma unroll
        for (int nt = 0; nt < 8; ++nt) {
            int cA = j0 + wj*64 + nt*8 + 2*cc;
            atomicMin(&g_m2[r0*N_ + cA],       __float_as_uint(dmin[mt][nt][0]));
            atomicMin(&g_m2[r0*N_ + cA + 1],   __float_as_uint(dmin[mt][nt][1]));
            atomicMin(&g_m2[(r0+8)*N_ + cA],   __float_as_uint(dmin[mt][nt][2]));
            atomicMin(&g_m2[(r0+8)*N_ + cA+1], __float_as_uint(dmin[mt][nt][3]));
        }
    }
}

// ---------------- chamfer reductions (sqrt here) ----------------
__global__ void k_red1() {
    int idx = blockIdx.x * blockDim.x + threadIdx.x;
    int stride = gridDim.x * blockDim.x;
    float s = 0.f;
    for (int i = idx; i < B_*N_; i += stride) s += sqrtf(__uint_as_float(g_m1[i]));
    s = blockReduceSum(s);
    if (threadIdx.x == 0) atomicAdd(&g_s1, (double)s);
}
__global__ void k_red2() {
    int idx = blockIdx.x * blockDim.x + threadIdx.x;
    int stride = gridDim.x * blockDim.x;
    float s = 0.f;
    for (int i = idx; i < N_*N_; i += stride) s += sqrtf(__uint_as_float(g_m2[i]));
    s = blockReduceSum(s);
    if (threadIdx.x == 0) atomicAdd(&g_s2, (double)s);
}

// ---------------- EMD: key transform ----------------
__global__ void k_transform(const float* __restrict__ pred, const float* __restrict__ target) {
    int i = blockIdx.x * blockDim.x + threadIdx.x;
    int stride = gridDim.x * blockDim.x;
    for (int x = i; x < NSEG*NDF; x += stride) {
        float v = (x < TOT) ? pred[x] : target[x - TOT];
        unsigned u = __float_as_uint(v);
        g_buf0[x] = (u & 0x80000000u) ? ~u : (u | 0x80000000u);
    }
}

// ---------------- radix sort (8-bit digits, 4 passes) ----------------
__global__ void k_hist(int pass) {
    const unsigned* __restrict__ src = (pass & 1) ? g_buf1 : g_buf0;
    int shift = pass * 8;
    __shared__ unsigned h[256];
    int t = threadIdx.x;
    h[t] = 0;
    __syncthreads();
    size_t base = (size_t)blockIdx.x * 4096;
    #pragma unroll
    for (int i = 0; i < 16; ++i) {
        unsigned k = src[base + i*256 + t];
        atomicAdd(&h[(k >> shift) & 255u], 1u);
    }
    __syncthreads();
    g_hist[blockIdx.x * 256 + t] = h[t];
}

__global__ void k_scan() {
    int seg = blockIdx.x;
    int bin = threadIdx.x;
    size_t base_idx = (size_t)seg * SEG_BLOCKS * 256 + bin;
    unsigned total = 0;
    #pragma unroll
    for (int blk = 0; blk < SEG_BLOCKS; ++blk) total += g_hist[base_idx + (size_t)blk*256];
    int lane = bin & 31, w = bin >> 5;
    unsigned x = total;
    #pragma unroll
    for (int o = 1; o < 32; o <<= 1) {
        unsigned y = __shfl_up_sync(0xffffffffu, x, o);
        if (lane >= o) x += y;
    }
    __shared__ unsigned wsum[8];
    if (lane == 31) wsum[w] = x;
    __syncthreads();
    if (threadIdx.x < 8) {
        unsigned v = wsum[threadIdx.x];
        #pragma unroll
        for (int o = 1; o < 8; o <<= 1) {
            unsigned y = __shfl_up_sync(0xffu, v, o);
            if ((int)threadIdx.x >= o) v += y;
        }
        wsum[threadIdx.x] = v;
    }
    __syncthreads();
    unsigned incl = x + (w > 0 ? wsum[w-1] : 0u);
    unsigned run = incl - total;  // segment-local digit start
    for (int blk = 0; blk < SEG_BLOCKS; ++blk) {
        unsigned v = g_hist[base_idx + (size_t)blk*256];
        g_hist[base_idx + (size_t)blk*256] = run;
        run += v;
    }
}

__global__ void k_scatter(int pass) {
    const unsigned* __restrict__ src = (pass & 1) ? g_buf1 : g_buf0;
    unsigned* __restrict__ dst       = (pass & 1) ? g_buf0 : g_buf1;
    int shift = pass * 8;
    __shared__ unsigned wh[8][256];
    int t = threadIdx.x, lane = t & 31, w = t >> 5;
    #pragma unroll
    for (int i = t; i < 2048; i += 256) ((unsigned*)wh)[i] = 0;
    __syncthreads();
    int blk = blockIdx.x;
    size_t segbase = (size_t)(blk / SEG_BLOCKS) * NDF;
    size_t base = (size_t)blk * 4096 + (size_t)w * 512;
    unsigned key[16];
    unsigned short rk[16];
    unsigned char dg[16];
    #pragma unroll
    for (int i = 0; i < 16; ++i) {
        unsigned k = src[base + i*32 + lane];
        key[i] = k;
        unsigned d = (k >> shift) & 255u;
        dg[i] = (unsigned char)d;
        unsigned peers = __match_any_sync(0xffffffffu, d);
        int leader = __ffs(peers) - 1;
        unsigned lr = __popc(peers & ((1u << lane) - 1u));
        unsigned bcnt = 0;
        if (lane == leader) { bcnt = wh[w][d]; wh[w][d] = bcnt + __popc(peers); }
        bcnt = __shfl_sync(0xffffffffu, bcnt, leader);
        rk[i] = (unsigned short)(bcnt + lr);
        __syncwarp();
    }
    __syncthreads();
    // thread t owns digit t: convert per-warp counts to absolute offsets
    {
        unsigned run = g_hist[(size_t)blk * 256 + t];
        #pragma unroll
        for (int ww = 0; ww < 8; ++ww) {
            unsigned c = wh[ww][t];
            wh[ww][t] = run;
            run += c;
        }
    }
    __syncthreads();
    #pragma unroll
    for (int i = 0; i < 16; ++i)
        dst[segbase + wh[w][dg[i]] + rk[i]] = key[i];
}

// ---------------- EMD reduce ----------------
__global__ void k_emd() {
    int b = blockIdx.x >> 3;
    int chunk = blockIdx.x & 7;
    const unsigned* p = g_buf0 + (size_t)b * NDF + (size_t)chunk * (NDF/8);
    const unsigned* q = g_buf0 + (size_t)(32 + b) * NDF + (size_t)chunk * (NDF/8);
    float s = 0.f;
    for (int i = threadIdx.x; i < NDF/8; i += blockDim.x)
        s += fabsf(keydec(p[i]) - keydec(q[i]));
    s = blockReduceSum(s);
    if (threadIdx.x == 0) atomicAdd(&g_emd[b], (double)s);
}

// ---------------- final combine ----------------
__global__ void k_final(float* out) {
    int b = threadIdx.x;
    if (b < B_) {
        double mae  = g_mae / (double)TOT;
        double cham = g_s1 / (double)(B_*N_) + g_s2 / (double)(N_*N_);
        out[b] = (float)(mae + cham + g_emd[b] / (double)NDF);
    }
}

extern "C" void kernel_launch(void* const* d_in, const int* in_sizes, int n_in,
                              void* d_out, int out_size) {
    const float* pred   = (const float*)d_in[0];
    const float* target = (const float*)d_in[1];
    float* out = (float*)d_out;

    cudaFuncSetAttribute(k_chamfer, cudaFuncAttributeMaxDynamicSharedMemorySize, CHAM_SMEM);

    k_init<<<256, 256>>>();
    k_maenorm<<<256, 256>>>(pred, target);
    k_transform<<<512, 256>>>(pred, target);
    k_chamfer<<<dim3(8, 8, 4), 256, CHAM_SMEM>>>(pred, target);
    k_red1<<<64, 256>>>();
    k_red2<<<256, 256>>>();
    for (int pass = 0; pass < 4; ++pass) {
        k_hist<<<RADIX_BLOCKS, 256>>>(pass);
        k_scan<<<NSEG, 256>>>();
        k_scatter<<<RADIX_BLOCKS, 256>>>(pass);
    }
    k_emd<<<256, 256>>>();
    k_final<<<1, 32>>>(out);
}

// round 4
// speedup vs baseline: 1.0031x; 1.0031x over previous
#include <cuda_runtime.h>
#include <cstdint>

#define B_  32
#define N_  1024
#define D_  128
#define NDF (N_*D_)          // 131072 per batch per tensor
#define TOT (B_*N_*D_)       // 4194304
#define NSEG 64
#define SEG_BLOCKS 32        // 131072/4096
#define RADIX_BLOCKS (NSEG*SEG_BLOCKS)

// ---------------- device scratch ----------------
__device__ float    g_normP[B_*N_];
__device__ float    g_normT[B_*N_];
__device__ unsigned g_m1[B_*N_];       // min_i d^2 (float bits)
__device__ unsigned g_m2[N_*N_];       // min_b d^2 (float bits)
__device__ double   g_mae, g_s1, g_s2;
__device__ double   g_emd[B_];
__device__ unsigned g_buf0[NSEG*NDF];
__device__ unsigned g_buf1[NSEG*NDF];
__device__ unsigned g_hist[RADIX_BLOCKS*256];

// ---------------- helpers ----------------
__device__ __forceinline__ unsigned f2tf(float x) {
    unsigned r; asm("cvt.rna.tf32.f32 %0, %1;" : "=r"(r) : "f"(x)); return r;
}
__device__ __forceinline__ void mma_tf32(float* c, const unsigned* a, const unsigned* b) {
    asm volatile(
        "mma.sync.aligned.m16n8k8.row.col.f32.tf32.tf32.f32 "
        "{%0,%1,%2,%3}, {%4,%5,%6,%7}, {%8,%9}, {%0,%1,%2,%3};\n"
        : "+f"(c[0]), "+f"(c[1]), "+f"(c[2]), "+f"(c[3])
        : "r"(a[0]), "r"(a[1]), "r"(a[2]), "r"(a[3]), "r"(b[0]), "r"(b[1]));
}
__device__ __forceinline__ float blockReduceSum(float v) {
    #pragma unroll
    for (int o = 16; o; o >>= 1) v += __shfl_xor_sync(0xffffffffu, v, o);
    __shared__ float sm[8];
    int lane = threadIdx.x & 31, w = threadIdx.x >> 5;
    if (lane == 0) sm[w] = v;
    __syncthreads();
    if (w == 0) {
        v = (lane < 8) ? sm[lane] : 0.f;
        #pragma unroll
        for (int o = 4; o; o >>= 1) v += __shfl_xor_sync(0xffffffffu, v, o);
    }
    return v;  // valid on thread 0
}
__device__ __forceinline__ float keydec(unsigned u) {
    unsigned bits = (u & 0x80000000u) ? (u ^ 0x80000000u) : ~u;
    return __uint_as_float(bits);
}

// ---------------- init ----------------
__global__ void k_init() {
    int i = blockIdx.x * blockDim.x + threadIdx.x;
    int stride = gridDim.x * blockDim.x;
    for (int x = i; x < N_*N_; x += stride) g_m2[x] = 0x7F800000u;
    for (int x = i; x < B_*N_; x += stride) g_m1[x] = 0x7F800000u;
    if (i == 0) { g_mae = 0.0; g_s1 = 0.0; g_s2 = 0.0; }
    if (i < B_) g_emd[i] = 0.0;
}

// ---------------- MAE + row squared norms (warp per row) ----------------
__global__ void k_maenorm(const float* __restrict__ pred, const float* __restrict__ target) {
    const int lane = threadIdx.x & 31;
    const int gw = (blockIdx.x * blockDim.x + threadIdx.x) >> 5;
    const int nw = (gridDim.x * blockDim.x) >> 5;
    float macc = 0.f;
    for (int row = gw; row < B_*N_; row += nw) {
        float4 p = reinterpret_cast<const float4*>(pred)[row*32 + lane];
        float4 t = reinterpret_cast<const float4*>(target)[row*32 + lane];
        float np = p.x*p.x + p.y*p.y + p.z*p.z + p.w*p.w;
        float nt = t.x*t.x + t.y*t.y + t.z*t.z + t.w*t.w;
        float m  = fabsf(p.x-t.x)+fabsf(p.y-t.y)+fabsf(p.z-t.z)+fabsf(p.w-t.w);
        #pragma unroll
        for (int o = 16; o; o >>= 1) {
            np += __shfl_xor_sync(0xffffffffu, np, o);
            nt += __shfl_xor_sync(0xffffffffu, nt, o);
            m  += __shfl_xor_sync(0xffffffffu, m,  o);
        }
        if (lane == 0) { g_normP[row] = np; g_normT[row] = nt; macc += m; }
    }
    __shared__ float bsum;
    if (threadIdx.x == 0) bsum = 0.f;
    __syncthreads();
    if (lane == 0) atomicAdd(&bsum, macc);
    __syncthreads();
    if (threadIdx.x == 0) atomicAdd(&g_mae, (double)bsum);
}

// ---------------- chamfer: tf32 MMA over squared distances ----------------
#define TI 128
#define TJ 128
#define BB 8
#define PAD 132
#define CHAM_SMEM ((2*128*PAD + 256) * 4)

__global__ void __launch_bounds__(256, 1)
k_chamfer(const float* __restrict__ pred, const float* __restrict__ target) {
    extern __shared__ unsigned smem_u[];
    unsigned* As = smem_u;                 // [128][PAD]
    unsigned* Bs = smem_u + 128*PAD;       // [128][PAD]
    float* sNp = (float*)(smem_u + 2*128*PAD);  // [128]
    float* sNt = sNp + 128;                     // [128]

    const int tid  = threadIdx.x;
    const int lane = tid & 31;
    const int warp = tid >> 5;
    const int wi = warp >> 1;   // 0..3
    const int wj = warp & 1;    // 0..1
    const int g  = lane >> 2;   // 0..7
    const int cc = lane & 3;    // 0..3

    const int i0 = blockIdx.x * TI;
    const int j0 = blockIdx.y * TJ;
    const int b0 = blockIdx.z * BB;

    float dmin[2][8][4];
    #pragma unroll
    for (int mt = 0; mt < 2; mt++)
        #pragma unroll
        for (int nt = 0; nt < 8; nt++)
            #pragma unroll
            for (int q = 0; q < 4; q++) dmin[mt][nt][q] = 3.4e38f;

    for (int bi = 0; bi < BB; ++bi) {
        const int b = b0 + bi;
        __syncthreads();
        {
            const float4* Ag = reinterpret_cast<const float4*>(pred   + ((size_t)b*N_ + i0) * D_);
            const float4* Bg = reinterpret_cast<const float4*>(target + ((size_t)b*N_ + j0) * D_);
            #pragma unroll
            for (int r = 0; r < 16; ++r) {
                int idx = r*256 + tid;
                int row = idx >> 5, c4 = idx & 31;
                float4 va = Ag[row*32 + c4];
                float4 vb = Bg[row*32 + c4];
                uint4 ua = make_uint4(f2tf(va.x), f2tf(va.y), f2tf(va.z), f2tf(va.w));
                uint4 ub = make_uint4(f2tf(vb.x), f2tf(vb.y), f2tf(vb.z), f2tf(vb.w));
                *reinterpret_cast<uint4*>(&As[row*PAD + c4*4]) = ua;
                *reinterpret_cast<uint4*>(&Bs[row*PAD + c4*4]) = ub;
            }
            if (tid < 128) sNp[tid] = g_normP[b*N_ + i0 + tid];
            else           sNt[tid-128] = g_normT[b*N_ + j0 + (tid-128)];
        }
        __syncthreads();

        float acc[2][8][4];
        #pragma unroll
        for (int mt = 0; mt < 2; mt++)
            #pragma unroll
            for (int nt = 0; nt < 8; nt++)
                #pragma unroll
                for (int q = 0; q < 4; q++) acc[mt][nt][q] = 0.f;

        #pragma unroll 4
        for (int k0 = 0; k0 < D_; k0 += 8) {
            unsigned a[2][4], bf[8][2];
            #pragma unroll
            for (int mt = 0; mt < 2; ++mt) {
                int r0 = wi*32 + mt*16 + g;
                a[mt][0] = As[r0*PAD + k0 + cc];
                a[mt][1] = As[(r0+8)*PAD + k0 + cc];
                a[mt][2] = As[r0*PAD + k0 + cc + 4];
                a[mt][3] = As[(r0+8)*PAD + k0 + cc + 4];
            }
            #pragma unroll
            for (int nt = 0; nt < 8; ++nt) {
                int jr = wj*64 + nt*8 + g;
                bf[nt][0] = Bs[jr*PAD + k0 + cc];
                bf[nt][1] = Bs[jr*PAD + k0 + cc + 4];
            }
            #pragma unroll
            for (int mt = 0; mt < 2; ++mt)
                #pragma unroll
                for (int nt = 0; nt < 8; ++nt)
                    mma_tf32(acc[mt][nt], a[mt], bf[nt]);
        }

        float nP[2][2];
        #pragma unroll
        for (int mt = 0; mt < 2; ++mt) {
            int r0 = wi*32 + mt*16 + g;
            nP[mt][0] = sNp[r0];
            nP[mt][1] = sNp[r0+8];
        }
        #pragma unroll
        for (int nt = 0; nt < 8; ++nt) {
            int cA = wj*64 + nt*8 + 2*cc;
            float nt0 = sNt[cA], nt1 = sNt[cA+1];
            float cm0 = 3.4e38f, cm1 = 3.4e38f;
            #pragma unroll
            for (int mt = 0; mt < 2; ++mt) {
                float s0 = fmaxf(fmaf(-2.f, acc[mt][nt][0], nP[mt][0] + nt0), 1e-12f);
                float s1 = fmaxf(fmaf(-2.f, acc[mt][nt][1], nP[mt][0] + nt1), 1e-12f);
                float s2 = fmaxf(fmaf(-2.f, acc[mt][nt][2], nP[mt][1] + nt0), 1e-12f);
                float s3 = fmaxf(fmaf(-2.f, acc[mt][nt][3], nP[mt][1] + nt1), 1e-12f);
                dmin[mt][nt][0] = fminf(dmin[mt][nt][0], s0);
                dmin[mt][nt][1] = fminf(dmin[mt][nt][1], s1);
                dmin[mt][nt][2] = fminf(dmin[mt][nt][2], s2);
                dmin[mt][nt][3] = fminf(dmin[mt][nt][3], s3);
                cm0 = fminf(cm0, fminf(s0, s2));
                cm1 = fminf(cm1, fminf(s1, s3));
            }
            #pragma unroll
            for (int o = 4; o <= 16; o <<= 1) {
                cm0 = fminf(cm0, __shfl_xor_sync(0xffffffffu, cm0, o));
                cm1 = fminf(cm1, __shfl_xor_sync(0xffffffffu, cm1, o));
            }
            if (g == 0) {
                atomicMin(&g_m1[b*N_ + j0 + cA],     __float_as_uint(cm0));
                atomicMin(&g_m1[b*N_ + j0 + cA + 1], __float_as_uint(cm1));
            }
        }
    }

    #pragma unroll
    for (int mt = 0; mt < 2; ++mt) {
        int r0 = i0 + wi*32 + mt*16 + g;
        #pragma unroll
        for (int nt = 0; nt < 8; ++nt) {
            int cA = j0 + wj*64 + nt*8 + 2*cc;
            atomicMin(&g_m2[r0*N_ + cA],       __float_as_uint(dmin[mt][nt][0]));
            atomicMin(&g_m2[r0*N_ + cA + 1],   __float_as_uint(dmin[mt][nt][1]));
            atomicMin(&g_m2[(r0+8)*N_ + cA],   __float_as_uint(dmin[mt][nt][2]));
            atomicMin(&g_m2[(r0+8)*N_ + cA+1], __float_as_uint(dmin[mt][nt][3]));
        }
    }
}

// ---------------- chamfer reductions (sqrt here) ----------------
__global__ void k_red1() {
    int idx = blockIdx.x * blockDim.x + threadIdx.x;
    int stride = gridDim.x * blockDim.x;
    float s = 0.f;
    for (int i = idx; i < B_*N_; i += stride) s += sqrtf(__uint_as_float(g_m1[i]));
    s = blockReduceSum(s);
    if (threadIdx.x == 0) atomicAdd(&g_s1, (double)s);
}
__global__ void k_red2() {
    int idx = blockIdx.x * blockDim.x + threadIdx.x;
    int stride = gridDim.x * blockDim.x;
    float s = 0.f;
    for (int i = idx; i < N_*N_; i += stride) s += sqrtf(__uint_as_float(g_m2[i]));
    s = blockReduceSum(s);
    if (threadIdx.x == 0) atomicAdd(&g_s2, (double)s);
}

// ---------------- EMD: key transform ----------------
__global__ void k_transform(const float* __restrict__ pred, const float* __restrict__ target) {
    int i = blockIdx.x * blockDim.x + threadIdx.x;
    int stride = gridDim.x * blockDim.x;
    for (int x = i; x < NSEG*NDF; x += stride) {
        float v = (x < TOT) ? pred[x] : target[x - TOT];
        unsigned u = __float_as_uint(v);
        g_buf0[x] = (u & 0x80000000u) ? ~u : (u | 0x80000000u);
    }
}

// ---------------- radix sort (8-bit digits, 4 passes) ----------------
__global__ void k_hist(int pass) {
    const unsigned* __restrict__ src = (pass & 1) ? g_buf1 : g_buf0;
    int shift = pass * 8;
    __shared__ unsigned h[256];
    int t = threadIdx.x;
    h[t] = 0;
    __syncthreads();
    size_t base = (size_t)blockIdx.x * 4096;
    #pragma unroll
    for (int i = 0; i < 16; ++i) {
        unsigned k = src[base + i*256 + t];
        atomicAdd(&h[(k >> shift) & 255u], 1u);
    }
    __syncthreads();
    g_hist[blockIdx.x * 256 + t] = h[t];
}

__global__ void k_scan() {
    int seg = blockIdx.x;
    int bin = threadIdx.x;
    size_t base_idx = (size_t)seg * SEG_BLOCKS * 256 + bin;
    unsigned total = 0;
    #pragma unroll
    for (int blk = 0; blk < SEG_BLOCKS; ++blk) total += g_hist[base_idx + (size_t)blk*256];
    int lane = bin & 31, w = bin >> 5;
    unsigned x = total;
    #pragma unroll
    for (int o = 1; o < 32; o <<= 1) {
        unsigned y = __shfl_up_sync(0xffffffffu, x, o);
        if (lane >= o) x += y;
    }
    __shared__ unsigned wsum[8];
    if (lane == 31) wsum[w] = x;
    __syncthreads();
    if (threadIdx.x < 8) {
        unsigned v = wsum[threadIdx.x];
        #pragma unroll
        for (int o = 1; o < 8; o <<= 1) {
            unsigned y = __shfl_up_sync(0xffu, v, o);
            if ((int)threadIdx.x >= o) v += y;
        }
        wsum[threadIdx.x] = v;
    }
    __syncthreads();
    unsigned incl = x + (w > 0 ? wsum[w-1] : 0u);
    unsigned run = incl - total;  // segment-local digit start
    for (int blk = 0; blk < SEG_BLOCKS; ++blk) {
        unsigned v = g_hist[base_idx + (size_t)blk*256];
        g_hist[base_idx + (size_t)blk*256] = run;
        run += v;
    }
}

__global__ void k_scatter(int pass) {
    const unsigned* __restrict__ src = (pass & 1) ? g_buf1 : g_buf0;
    unsigned* __restrict__ dst       = (pass & 1) ? g_buf0 : g_buf1;
    int shift = pass * 8;
    __shared__ unsigned wh[8][256];
    int t = threadIdx.x, lane = t & 31, w = t >> 5;
    #pragma unroll
    for (int i = t; i < 2048; i += 256) ((unsigned*)wh)[i] = 0;
    __syncthreads();
    int blk = blockIdx.x;
    size_t segbase = (size_t)(blk / SEG_BLOCKS) * NDF;
    size_t base = (size_t)blk * 4096 + (size_t)w * 512;
    unsigned key[16];
    unsigned short rk[16];
    unsigned char dg[16];
    #pragma unroll
    for (int i = 0; i < 16; ++i) {
        unsigned k = src[base + i*32 + lane];
        key[i] = k;
        unsigned d = (k >> shift) & 255u;
        dg[i] = (unsigned char)d;
        unsigned peers = __match_any_sync(0xffffffffu, d);
        int leader = __ffs(peers) - 1;
        unsigned lr = __popc(peers & ((1u << lane) - 1u));
        unsigned bcnt = 0;
        if (lane == leader) { bcnt = wh[w][d]; wh[w][d] = bcnt + __popc(peers); }
        bcnt = __shfl_sync(0xffffffffu, bcnt, leader);
        rk[i] = (unsigned short)(bcnt + lr);
        __syncwarp();
    }
    __syncthreads();
    // thread t owns digit t: convert per-warp counts to absolute offsets
    {
        unsigned run = g_hist[(size_t)blk * 256 + t];
        #pragma unroll
        for (int ww = 0; ww < 8; ++ww) {
            unsigned c = wh[ww][t];
            wh[ww][t] = run;
            run += c;
        }
    }
    __syncthreads();
    #pragma unroll
    for (int i = 0; i < 16; ++i)
        dst[segbase + wh[w][dg[i]] + rk[i]] = key[i];
}

// ---------------- EMD reduce ----------------
__global__ void k_emd() {
    int b = blockIdx.x >> 3;
    int chunk = blockIdx.x & 7;
    const unsigned* p = g_buf0 + (size_t)b * NDF + (size_t)chunk * (NDF/8);
    const unsigned* q = g_buf0 + (size_t)(32 + b) * NDF + (size_t)chunk * (NDF/8);
    float s = 0.f;
    for (int i = threadIdx.x; i < NDF/8; i += blockDim.x)
        s += fabsf(keydec(p[i]) - keydec(q[i]));
    s = blockReduceSum(s);
    if (threadIdx.x == 0) atomicAdd(&g_emd[b], (double)s);
}

// ---------------- final combine ----------------
__global__ void k_final(float* out) {
    int b = threadIdx.x;
    if (b < B_) {
        double mae  = g_mae / (double)TOT;
        double cham = g_s1 / (double)(B_*N_) + g_s2 / (double)(N_*N_);
        out[b] = (float)(mae + cham + g_emd[b] / (double)NDF);
    }
}

extern "C" void kernel_launch(void* const* d_in, const int* in_sizes, int n_in,
                              void* d_out, int out_size) {
    const float* pred   = (const float*)d_in[0];
    const float* target = (const float*)d_in[1];
    float* out = (float*)d_out;

    cudaFuncSetAttribute(k_chamfer, cudaFuncAttributeMaxDynamicSharedMemorySize, CHAM_SMEM);

    k_init<<<256, 256>>>();
    k_maenorm<<<256, 256>>>(pred, target);
    k_transform<<<512, 256>>>(pred, target);
    k_chamfer<<<dim3(8, 8, 4), 256, CHAM_SMEM>>>(pred, target);
    k_red1<<<64, 256>>>();
    k_red2<<<256, 256>>>();
    for (int pass = 0; pass < 4; ++pass) {
        k_hist<<<RADIX_BLOCKS, 256>>>(pass);
        k_scan<<<NSEG, 256>>>();
        k_scatter<<<RADIX_BLOCKS, 256>>>(pass);
    }
    k_emd<<<256, 256>>>();
    k_final<<<1, 32>>>(out);
}

// round 5
// speedup vs baseline: 1.0399x; 1.0367x over previous
#include <cuda_runtime.h>
#include <cstdint>

#define B_  32
#define N_  1024
#define D_  128
#define NDF (N_*D_)          // 131072 per batch per tensor
#define TOT (B_*N_*D_)       // 4194304
#define NSEG 64
#define SEG_BLOCKS 32        // 131072/4096
#define RADIX_BLOCKS (NSEG*SEG_BLOCKS)   // 2048

// ---------------- device scratch ----------------
__device__ float    g_normP[B_*N_];
__device__ float    g_normT[B_*N_];
__device__ unsigned g_m1[B_*N_];       // min_i d^2 (float bits)
__device__ unsigned g_m2[N_*N_];       // min_b d^2 (float bits)
__device__ double   g_mae, g_s1, g_s2;
__device__ double   g_emd[B_];
__device__ unsigned g_buf0[NSEG*NDF];
__device__ unsigned g_buf1[NSEG*NDF];
__device__ unsigned g_h[4][RADIX_BLOCKS*256];   // per-pass per-block histograms/offsets

// ---------------- helpers ----------------
__device__ __forceinline__ unsigned f2tf(float x) {
    unsigned r; asm("cvt.rna.tf32.f32 %0, %1;" : "=r"(r) : "f"(x)); return r;
}
__device__ __forceinline__ void mma_tf32(float* c, const unsigned* a, const unsigned* b) {
    asm volatile(
        "mma.sync.aligned.m16n8k8.row.col.f32.tf32.tf32.f32 "
        "{%0,%1,%2,%3}, {%4,%5,%6,%7}, {%8,%9}, {%0,%1,%2,%3};\n"
        : "+f"(c[0]), "+f"(c[1]), "+f"(c[2]), "+f"(c[3])
        : "r"(a[0]), "r"(a[1]), "r"(a[2]), "r"(a[3]), "r"(b[0]), "r"(b[1]));
}
__device__ __forceinline__ float blockReduceSum(float v) {
    #pragma unroll
    for (int o = 16; o; o >>= 1) v += __shfl_xor_sync(0xffffffffu, v, o);
    __shared__ float sm[16];
    int lane = threadIdx.x & 31, w = threadIdx.x >> 5;
    int nw = (blockDim.x + 31) >> 5;
    if (lane == 0) sm[w] = v;
    __syncthreads();
    if (w == 0) {
        v = (lane < nw) ? sm[lane] : 0.f;
        #pragma unroll
        for (int o = 8; o; o >>= 1) v += __shfl_xor_sync(0xffffffffu, v, o);
    }
    return v;  // valid on thread 0
}
__device__ __forceinline__ float keydec(unsigned u) {
    unsigned bits = (u & 0x80000000u) ? (u ^ 0x80000000u) : ~u;
    return __uint_as_float(bits);
}

// ---------------- init ----------------
__global__ void k_init() {
    int i = blockIdx.x * blockDim.x + threadIdx.x;
    int stride = gridDim.x * blockDim.x;
    for (int x = i; x < N_*N_; x += stride) g_m2[x] = 0x7F800000u;
    for (int x = i; x < B_*N_; x += stride) g_m1[x] = 0x7F800000u;
    unsigned* h = &g_h[0][0];
    for (int x = i; x < 4*RADIX_BLOCKS*256; x += stride) h[x] = 0u;
    if (i == 0) { g_mae = 0.0; g_s1 = 0.0; g_s2 = 0.0; }
    if (i < B_) g_emd[i] = 0.0;
}

// ---------------- MAE + row squared norms (warp per row) ----------------
__global__ void k_maenorm(const float* __restrict__ pred, const float* __restrict__ target) {
    const int lane = threadIdx.x & 31;
    const int gw = (blockIdx.x * blockDim.x + threadIdx.x) >> 5;
    const int nw = (gridDim.x * blockDim.x) >> 5;
    float macc = 0.f;
    for (int row = gw; row < B_*N_; row += nw) {
        float4 p = reinterpret_cast<const float4*>(pred)[row*32 + lane];
        float4 t = reinterpret_cast<const float4*>(target)[row*32 + lane];
        float np = p.x*p.x + p.y*p.y + p.z*p.z + p.w*p.w;
        float nt = t.x*t.x + t.y*t.y + t.z*t.z + t.w*t.w;
        float m  = fabsf(p.x-t.x)+fabsf(p.y-t.y)+fabsf(p.z-t.z)+fabsf(p.w-t.w);
        #pragma unroll
        for (int o = 16; o; o >>= 1) {
            np += __shfl_xor_sync(0xffffffffu, np, o);
            nt += __shfl_xor_sync(0xffffffffu, nt, o);
            m  += __shfl_xor_sync(0xffffffffu, m,  o);
        }
        if (lane == 0) { g_normP[row] = np; g_normT[row] = nt; macc += m; }
    }
    __shared__ float bsum;
    if (threadIdx.x == 0) bsum = 0.f;
    __syncthreads();
    if (lane == 0) atomicAdd(&bsum, macc);
    __syncthreads();
    if (threadIdx.x == 0) atomicAdd(&g_mae, (double)bsum);
}

// ---------------- chamfer: tf32 MMA over squared distances, 512 threads ----------------
#define TI 128
#define TJ 128
#define BB 8
#define PAD 132
#define CHAM_SMEM ((2*128*PAD + 256) * 4)

__global__ void __launch_bounds__(512, 1)
k_chamfer(const float* __restrict__ pred, const float* __restrict__ target) {
    extern __shared__ unsigned smem_u[];
    unsigned* As = smem_u;                 // [128][PAD]
    unsigned* Bs = smem_u + 128*PAD;       // [128][PAD]
    float* sNp = (float*)(smem_u + 2*128*PAD);  // [128]
    float* sNt = sNp + 128;                     // [128]

    const int tid  = threadIdx.x;
    const int lane = tid & 31;
    const int warp = tid >> 5;           // 0..15
    const int wi = warp >> 2;            // 0..3 (i direction, 32 rows each)
    const int wj = warp & 3;             // 0..3 (j direction, 32 cols each)
    const int g  = lane >> 2;            // 0..7
    const int cc = lane & 3;             // 0..3

    const int i0 = blockIdx.x * TI;
    const int j0 = blockIdx.y * TJ;
    const int b0 = blockIdx.z * BB;

    float dmin[2][4][4];
    #pragma unroll
    for (int mt = 0; mt < 2; mt++)
        #pragma unroll
        for (int nt = 0; nt < 4; nt++)
            #pragma unroll
            for (int q = 0; q < 4; q++) dmin[mt][nt][q] = 3.4e38f;

    for (int bi = 0; bi < BB; ++bi) {
        const int b = b0 + bi;
        __syncthreads();
        {
            const float4* Ag = reinterpret_cast<const float4*>(pred   + ((size_t)b*N_ + i0) * D_);
            const float4* Bg = reinterpret_cast<const float4*>(target + ((size_t)b*N_ + j0) * D_);
            #pragma unroll
            for (int r = 0; r < 8; ++r) {
                int idx = r*512 + tid;
                int row = idx >> 5, c4 = idx & 31;
                float4 va = Ag[row*32 + c4];
                float4 vb = Bg[row*32 + c4];
                uint4 ua = make_uint4(f2tf(va.x), f2tf(va.y), f2tf(va.z), f2tf(va.w));
                uint4 ub = make_uint4(f2tf(vb.x), f2tf(vb.y), f2tf(vb.z), f2tf(vb.w));
                *reinterpret_cast<uint4*>(&As[row*PAD + c4*4]) = ua;
                *reinterpret_cast<uint4*>(&Bs[row*PAD + c4*4]) = ub;
            }
            if (tid < 128)       sNp[tid] = g_normP[b*N_ + i0 + tid];
            else if (tid < 256)  sNt[tid-128] = g_normT[b*N_ + j0 + (tid-128)];
        }
        __syncthreads();

        float acc[2][4][4];
        #pragma unroll
        for (int mt = 0; mt < 2; mt++)
            #pragma unroll
            for (int nt = 0; nt < 4; nt++)
                #pragma unroll
                for (int q = 0; q < 4; q++) acc[mt][nt][q] = 0.f;

        #pragma unroll 4
        for (int k0 = 0; k0 < D_; k0 += 8) {
            unsigned a[2][4], bf[4][2];
            #pragma unroll
            for (int mt = 0; mt < 2; ++mt) {
                int r0 = wi*32 + mt*16 + g;
                a[mt][0] = As[r0*PAD + k0 + cc];
                a[mt][1] = As[(r0+8)*PAD + k0 + cc];
                a[mt][2] = As[r0*PAD + k0 + cc + 4];
                a[mt][3] = As[(r0+8)*PAD + k0 + cc + 4];
            }
            #pragma unroll
            for (int nt = 0; nt < 4; ++nt) {
                int jr = wj*32 + nt*8 + g;
                bf[nt][0] = Bs[jr*PAD + k0 + cc];
                bf[nt][1] = Bs[jr*PAD + k0 + cc + 4];
            }
            #pragma unroll
            for (int mt = 0; mt < 2; ++mt)
                #pragma unroll
                for (int nt = 0; nt < 4; ++nt)
                    mma_tf32(acc[mt][nt], a[mt], bf[nt]);
        }

        float nP[2][2];
        #pragma unroll
        for (int mt = 0; mt < 2; ++mt) {
            int r0 = wi*32 + mt*16 + g;
            nP[mt][0] = sNp[r0];
            nP[mt][1] = sNp[r0+8];
        }
        #pragma unroll
        for (int nt = 0; nt < 4; ++nt) {
            int cA = wj*32 + nt*8 + 2*cc;
            float nt0 = sNt[cA], nt1 = sNt[cA+1];
            float cm0 = 3.4e38f, cm1 = 3.4e38f;
            #pragma unroll
            for (int mt = 0; mt < 2; ++mt) {
                float s0 = fmaxf(fmaf(-2.f, acc[mt][nt][0], nP[mt][0] + nt0), 1e-12f);
                float s1 = fmaxf(fmaf(-2.f, acc[mt][nt][1], nP[mt][0] + nt1), 1e-12f);
                float s2 = fmaxf(fmaf(-2.f, acc[mt][nt][2], nP[mt][1] + nt0), 1e-12f);
                float s3 = fmaxf(fmaf(-2.f, acc[mt][nt][3], nP[mt][1] + nt1), 1e-12f);
                dmin[mt][nt][0] = fminf(dmin[mt][nt][0], s0);
                dmin[mt][nt][1] = fminf(dmin[mt][nt][1], s1);
                dmin[mt][nt][2] = fminf(dmin[mt][nt][2], s2);
                dmin[mt][nt][3] = fminf(dmin[mt][nt][3], s3);
                cm0 = fminf(cm0, fminf(s0, s2));
                cm1 = fminf(cm1, fminf(s1, s3));
            }
            #pragma unroll
            for (int o = 4; o <= 16; o <<= 1) {
                cm0 = fminf(cm0, __shfl_xor_sync(0xffffffffu, cm0, o));
                cm1 = fminf(cm1, __shfl_xor_sync(0xffffffffu, cm1, o));
            }
            if (g == 0) {
                atomicMin(&g_m1[b*N_ + j0 + cA],     __float_as_uint(cm0));
                atomicMin(&g_m1[b*N_ + j0 + cA + 1], __float_as_uint(cm1));
            }
        }
    }

    #pragma unroll
    for (int mt = 0; mt < 2; ++mt) {
        int r0 = i0 + wi*32 + mt*16 + g;
        #pragma unroll
        for (int nt = 0; nt < 4; ++nt) {
            int cA = j0 + wj*32 + nt*8 + 2*cc;
            atomicMin(&g_m2[r0*N_ + cA],       __float_as_uint(dmin[mt][nt][0]));
            atomicMin(&g_m2[r0*N_ + cA + 1],   __float_as_uint(dmin[mt][nt][1]));
            atomicMin(&g_m2[(r0+8)*N_ + cA],   __float_as_uint(dmin[mt][nt][2]));
            atomicMin(&g_m2[(r0+8)*N_ + cA+1], __float_as_uint(dmin[mt][nt][3]));
        }
    }
}

// ---------------- chamfer reductions (sqrt here) ----------------
__global__ void k_red1() {
    int idx = blockIdx.x * blockDim.x + threadIdx.x;
    int stride = gridDim.x * blockDim.x;
    float s = 0.f;
    for (int i = idx; i < B_*N_; i += stride) s += sqrtf(__uint_as_float(g_m1[i]));
    s = blockReduceSum(s);
    if (threadIdx.x == 0) atomicAdd(&g_s1, (double)s);
}
__global__ void k_red2() {
    int idx = blockIdx.x * blockDim.x + threadIdx.x;
    int stride = gridDim.x * blockDim.x;
    float s = 0.f;
    for (int i = idx; i < N_*N_; i += stride) s += sqrtf(__uint_as_float(g_m2[i]));
    s = blockReduceSum(s);
    if (threadIdx.x == 0) atomicAdd(&g_s2, (double)s);
}

// ---------------- EMD: key transform + pass-0 per-block histogram ----------------
__global__ void k_transform(const float* __restrict__ pred, const float* __restrict__ target) {
    __shared__ unsigned h[256];
    int t = threadIdx.x;
    h[t] = 0;
    __syncthreads();
    size_t base = (size_t)blockIdx.x * 4096;
    #pragma unroll
    for (int i = 0; i < 16; ++i) {
        size_t x = base + i*256 + t;
        float v = (x < TOT) ? pred[x] : target[x - TOT];
        unsigned u = __float_as_uint(v);
        u = (u & 0x80000000u) ? ~u : (u | 0x80000000u);
        g_buf0[x] = u;
        atomicAdd(&h[u & 255u], 1u);
    }
    __syncthreads();
    g_h[0][blockIdx.x * 256 + t] = h[t];
}

// ---------------- per-segment scan of per-block histograms -> offsets ----------------
__global__ void k_scan(int pass) {
    unsigned* __restrict__ hist = g_h[pass];
    int seg = blockIdx.x;
    int bin = threadIdx.x;
    size_t base_idx = (size_t)seg * SEG_BLOCKS * 256 + bin;
    unsigned total = 0;
    #pragma unroll
    for (int blk = 0; blk < SEG_BLOCKS; ++blk) total += hist[base_idx + (size_t)blk*256];
    int lane = bin & 31, w = bin >> 5;
    unsigned x = total;
    #pragma unroll
    for (int o = 1; o < 32; o <<= 1) {
        unsigned y = __shfl_up_sync(0xffffffffu, x, o);
        if (lane >= o) x += y;
    }
    __shared__ unsigned wsum[8];
    if (lane == 31) wsum[w] = x;
    __syncthreads();
    if (threadIdx.x < 8) {
        unsigned v = wsum[threadIdx.x];
        #pragma unroll
        for (int o = 1; o < 8; o <<= 1) {
            unsigned y = __shfl_up_sync(0xffu, v, o, 8);
            if ((int)threadIdx.x >= o) v += y;
        }
        wsum[threadIdx.x] = v;
    }
    __syncthreads();
    unsigned incl = x + (w > 0 ? wsum[w-1] : 0u);
    unsigned run = incl - total;  // segment-relative digit start
    for (int blk = 0; blk < SEG_BLOCKS; ++blk) {
        unsigned v = hist[base_idx + (size_t)blk*256];
        hist[base_idx + (size_t)blk*256] = run;
        run += v;
    }
}

// ---------------- scatter with smem staging + next-pass histogram ----------------
__global__ void k_scatter(int pass) {
    const unsigned* __restrict__ src = (pass & 1) ? g_buf1 : g_buf0;
    unsigned* __restrict__ dst       = (pass & 1) ? g_buf0 : g_buf1;
    const int shift = pass * 8;
    __shared__ unsigned wh[8][256];
    __shared__ unsigned dstart[256];   // block-local digit start
    __shared__ unsigned goff[256];     // segment-relative base minus dstart
    __shared__ unsigned stage[4096];
    __shared__ unsigned wsum[8];
    int t = threadIdx.x, lane = t & 31, w = t >> 5;
    #pragma unroll
    for (int i = t; i < 2048; i += 256) ((unsigned*)wh)[i] = 0;
    __syncthreads();
    int blk = blockIdx.x;
    int seg = blk / SEG_BLOCKS;
    size_t segbase = (size_t)seg * NDF;
    size_t base = (size_t)blk * 4096 + (size_t)w * 512;
    unsigned key[16];
    unsigned short rk[16];
    unsigned char dg[16];
    #pragma unroll
    for (int i = 0; i < 16; ++i) {
        unsigned k = src[base + i*32 + lane];
        key[i] = k;
        unsigned d = (k >> shift) & 255u;
        dg[i] = (unsigned char)d;
        unsigned peers = __match_any_sync(0xffffffffu, d);
        int leader = __ffs(peers) - 1;
        unsigned lr = __popc(peers & ((1u << lane) - 1u));
        unsigned bcnt = 0;
        if (lane == leader) { bcnt = wh[w][d]; wh[w][d] = bcnt + __popc(peers); }
        bcnt = __shfl_sync(0xffffffffu, bcnt, leader);
        rk[i] = (unsigned short)(bcnt + lr);
        __syncwarp();
    }
    __syncthreads();
    // thread t owns digit t: per-warp exclusive starts + block scan over digits
    unsigned c[8];
    unsigned tot = 0;
    #pragma unroll
    for (int ww = 0; ww < 8; ++ww) {
        unsigned v = wh[ww][t];
        c[ww] = tot;
        tot += v;
    }
    unsigned x = tot;
    #pragma unroll
    for (int o = 1; o < 32; o <<= 1) {
        unsigned y = __shfl_up_sync(0xffffffffu, x, o);
        if (lane >= o) x += y;
    }
    if (lane == 31) wsum[w] = x;
    __syncthreads();
    if (t < 8) {
        unsigned v = wsum[t];
        #pragma unroll
        for (int o = 1; o < 8; o <<= 1) {
            unsigned y = __shfl_up_sync(0xffu, v, o, 8);
            if (t >= o) v += y;
        }
        wsum[t] = v;
    }
    __syncthreads();
    unsigned ds = x + (w > 0 ? wsum[w-1] : 0u) - tot;   // exclusive digit start in block
    dstart[t] = ds;
    goff[t] = g_h[pass][(size_t)blk * 256 + t] - ds;    // segment-relative target minus local
    #pragma unroll
    for (int ww = 0; ww < 8; ++ww) wh[ww][t] = ds + c[ww];
    __syncthreads();
    // stage keys in block-sorted order
    #pragma unroll
    for (int i = 0; i < 16; ++i)
        stage[wh[w][dg[i]] + rk[i]] = key[i];
    __syncthreads();
    // linear read of staged keys -> run-coalesced global writes (+ next-pass hist)
    if (pass < 3) {
        unsigned* __restrict__ nh = g_h[pass + 1];
        int shift2 = shift + 8;
        #pragma unroll
        for (int i = 0; i < 16; ++i) {
            int idx = i*256 + t;
            unsigned k = stage[idx];
            unsigned d = (k >> shift) & 255u;
            unsigned gpos = goff[d] + idx;            // segment-relative dest
            dst[segbase + gpos] = k;
            unsigned dstblk = seg * SEG_BLOCKS + (gpos >> 12);
            atomicAdd(&nh[(size_t)dstblk * 256 + ((k >> shift2) & 255u)], 1u);
        }
    } else {
        #pragma unroll
        for (int i = 0; i < 16; ++i) {
            int idx = i*256 + t;
            unsigned k = stage[idx];
            unsigned d = (k >> shift) & 255u;
            dst[segbase + goff[d] + idx] = k;
        }
    }
}

// ---------------- EMD reduce ----------------
__global__ void k_emd() {
    int b = blockIdx.x >> 3;
    int chunk = blockIdx.x & 7;
    const unsigned* p = g_buf0 + (size_t)b * NDF + (size_t)chunk * (NDF/8);
    const unsigned* q = g_buf0 + (size_t)(32 + b) * NDF + (size_t)chunk * (NDF/8);
    float s = 0.f;
    for (int i = threadIdx.x; i < NDF/8; i += blockDim.x)
        s += fabsf(keydec(p[i]) - keydec(q[i]));
    s = blockReduceSum(s);
    if (threadIdx.x == 0) atomicAdd(&g_emd[b], (double)s);
}

// ---------------- final combine ----------------
__global__ void k_final(float* out) {
    int b = threadIdx.x;
    if (b < B_) {
        double mae  = g_mae / (double)TOT;
        double cham = g_s1 / (double)(B_*N_) + g_s2 / (double)(N_*N_);
        out[b] = (float)(mae + cham + g_emd[b] / (double)NDF);
    }
}

extern "C" void kernel_launch(void* const* d_in, const int* in_sizes, int n_in,
                              void* d_out, int out_size) {
    const float* pred   = (const float*)d_in[0];
    const float* target = (const float*)d_in[1];
    float* out = (float*)d_out;

    cudaFuncSetAttribute(k_chamfer, cudaFuncAttributeMaxDynamicSharedMemorySize, CHAM_SMEM);

    k_init<<<512, 256>>>();
    k_maenorm<<<256, 256>>>(pred, target);
    k_transform<<<RADIX_BLOCKS, 256>>>(pred, target);
    k_chamfer<<<dim3(8, 8, 4), 512, CHAM_SMEM>>>(pred, target);
    k_red1<<<64, 256>>>();
    k_red2<<<256, 256>>>();
    for (int pass = 0; pass < 4; ++pass) {
        k_scan<<<NSEG, 256>>>(pass);
        k_scatter<<<RADIX_BLOCKS, 256>>>(pass);
    }
    k_emd<<<256, 256>>>();
    k_final<<<1, 32>>>(out);
}